// round 13
// baseline (speedup 1.0000x reference)
#include <cuda_runtime.h>
#include <cuda_fp16.h>
#include <cstdint>

#define HEADS 8
#define HEAD_DIM 32
#define NPIX 1024
#define BATCH 16
#define CDIM 256
#define DIM 256
#define SCALE 0.17677669529663687f  /* 32^-0.5 */
#define LOG2E 1.4426950408889634f

// Scratch (allocation-free rule: __device__ globals)
__device__ __half g_xh[(size_t)BATCH * CDIM * NPIX];            // fp16 copy of x
__device__ __half g_wh[(size_t)4 * CDIM * DIM];                 // Wq,Wk,Wv,Wo hi
__device__ __half g_wl[(size_t)4 * CDIM * DIM];                 // Wq,Wk,Wv,Wo lo
__device__ __half g_q [(size_t)BATCH * HEADS * NPIX * HEAD_DIM];
__device__ __half g_k [(size_t)BATCH * HEADS * NPIX * HEAD_DIM]; // pre-scaled SCALE*log2e
__device__ __half g_v [(size_t)BATCH * HEADS * NPIX * HEAD_DIM];
__device__ __half g_ao[(size_t)BATCH * NPIX * DIM];

// ---------------- warp-MMA helpers (base ISA, no 'a' features) ---------------
__device__ __forceinline__ uint32_t smem_u32(const void* p) {
    uint32_t a;
    asm("{ .reg .u64 t; cvta.to.shared.u64 t, %1; cvt.u32.u64 %0, t; }"
        : "=r"(a) : "l"(p));
    return a;
}
__device__ __forceinline__ void ldm_x4(uint32_t& r0, uint32_t& r1,
                                       uint32_t& r2, uint32_t& r3, uint32_t a) {
    asm volatile("ldmatrix.sync.aligned.m8n8.x4.shared.b16 {%0,%1,%2,%3}, [%4];"
                 : "=r"(r0), "=r"(r1), "=r"(r2), "=r"(r3) : "r"(a));
}
__device__ __forceinline__ void ldm_x4t(uint32_t& r0, uint32_t& r1,
                                        uint32_t& r2, uint32_t& r3, uint32_t a) {
    asm volatile("ldmatrix.sync.aligned.m8n8.x4.trans.shared.b16 {%0,%1,%2,%3}, [%4];"
                 : "=r"(r0), "=r"(r1), "=r"(r2), "=r"(r3) : "r"(a));
}
__device__ __forceinline__ void mma16816(float* d, const uint32_t* a,
                                         uint32_t b0, uint32_t b1) {
    asm volatile(
        "mma.sync.aligned.m16n8k16.row.col.f32.f16.f16.f32 "
        "{%0,%1,%2,%3}, {%4,%5,%6,%7}, {%8,%9}, {%0,%1,%2,%3};"
        : "+f"(d[0]), "+f"(d[1]), "+f"(d[2]), "+f"(d[3])
        : "r"(a[0]), "r"(a[1]), "r"(a[2]), "r"(a[3]), "r"(b0), "r"(b1));
}
__device__ __forceinline__ uint32_t h2u(__half2 h) {
    return *reinterpret_cast<uint32_t*>(&h);
}
__device__ __forceinline__ uint32_t ex2_f16x2(uint32_t x) {
    uint32_t r;
    asm("ex2.approx.f16x2 %0, %1;" : "=r"(r) : "r"(x));
    return r;
}
__device__ __forceinline__ void split4(const float4 v,
                                       uint32_t& h01, uint32_t& h23,
                                       uint32_t& l01, uint32_t& l23) {
    const __half2 a = __floats2half2_rn(v.x, v.y);
    const __half2 b = __floats2half2_rn(v.z, v.w);
    const float2 fa = __half22float2(a);
    const float2 fb = __half22float2(b);
    h01 = h2u(a); h23 = h2u(b);
    l01 = h2u(__floats2half2_rn(v.x - fa.x, v.y - fa.y));
    l23 = h2u(__floats2half2_rn(v.z - fb.x, v.w - fb.y));
}
__device__ __forceinline__ int fsw(int row) { return (row ^ (row >> 2)) & 3; }

// cp.async (base ISA since sm_80)
__device__ __forceinline__ void cp16(uint32_t dst, const void* src) {
    asm volatile("cp.async.cg.shared.global [%0], [%1], 16;"
                 :: "r"(dst), "l"(src));
}
#define CP_COMMIT() asm volatile("cp.async.commit_group;" ::: "memory")
#define CP_WAIT1()  asm volatile("cp.async.wait_group 1;" ::: "memory")
#define CP_WAIT0()  asm volatile("cp.async.wait_group 0;" ::: "memory")

// ---------------------------------------------------------------------------
// Kernel 0a: one-shot x fp32 -> fp16.
// ---------------------------------------------------------------------------
__global__ __launch_bounds__(256) void xcvt_kernel(const float* __restrict__ x)
{
    const size_t i = ((size_t)blockIdx.x * 256 + threadIdx.x) * 8;
    const float4 a = *(const float4*)(x + i);
    const float4 b = *(const float4*)(x + i + 4);
    uint4 o;
    o.x = h2u(__floats2half2_rn(a.x, a.y));
    o.y = h2u(__floats2half2_rn(a.z, a.w));
    o.z = h2u(__floats2half2_rn(b.x, b.y));
    o.w = h2u(__floats2half2_rn(b.z, b.w));
    *(uint4*)(g_xh + i) = o;
}

// ---------------------------------------------------------------------------
// Kernel 0b: one-shot weight fp32 -> hi/lo fp16 split (Wq,Wk,Wv,Wo).
// Removes the 128x-redundant per-CTA split4 from qkv/oproj prologues.
// ---------------------------------------------------------------------------
__global__ __launch_bounds__(256) void wcvt_kernel(
    const float* __restrict__ Wq, const float* __restrict__ Wk,
    const float* __restrict__ Wv, const float* __restrict__ Wo)
{
    const int m = blockIdx.y;
    const float* W = (m == 0) ? Wq : (m == 1) ? Wk : (m == 2) ? Wv : Wo;
    const size_t i = ((size_t)blockIdx.x * 256 + threadIdx.x) * 8;
    const float4 a = *(const float4*)(W + i);
    const float4 b = *(const float4*)(W + i + 4);
    uint4 uh, ul;
    split4(a, uh.x, uh.y, ul.x, ul.y);
    split4(b, uh.z, uh.w, ul.z, ul.w);
    *(uint4*)(g_wh + (size_t)m * CDIM * DIM + i) = uh;
    *(uint4*)(g_wl + (size_t)m * CDIM * DIM + i) = ul;
}

// ---------------------------------------------------------------------------
// Kernel 1: fused QKV projection on HMMA, 2-term split: x_h*(W_h + W_l).
// All tile loads are now pure fp16 16B copies (x and W pre-converted).
// ---------------------------------------------------------------------------
__global__ __launch_bounds__(128) void qkv_kernel()
{
    __shared__ __align__(16) __half xh[32][136];   // [k][m], padded rows
    __shared__ __align__(16) __half wh[64][32];    // [j][k], chunk-swizzled
    __shared__ __align__(16) __half wl[64][32];

    const int nt = blockIdx.x;          // 0..11
    const int which = nt >> 2;          // 0=Q, 1=K, 2=V
    const int j0 = (nt & 3) * 64;
    const int m0 = blockIdx.y * 128;
    const int b  = blockIdx.z;
    const __half* wsh = g_wh + (size_t)which * CDIM * DIM;
    const __half* wsl = g_wl + (size_t)which * CDIM * DIM;
    const __half* xb = g_xh + (size_t)b * CDIM * NPIX;

    const int t = threadIdx.x, w = t >> 5, lane = t & 31;
    const int lr = lane & 7, lm = lane >> 3;
    const int warp_m = (w & 1) * 64, warp_j = (w >> 1) * 32;

    float acc[4][4][4];
#pragma unroll
    for (int mi = 0; mi < 4; mi++)
#pragma unroll
        for (int ji = 0; ji < 4; ji++)
#pragma unroll
            for (int r = 0; r < 4; r++) acc[mi][ji][r] = 0.f;

    for (int k0 = 0; k0 < CDIM; k0 += 32) {
        // x tile: 32k x 128m fp16, straight 16B copies
#pragma unroll
        for (int i = 0; i < 4; i++) {
            const int idx = i * 128 + t;
            const int kk = idx >> 4, c2 = idx & 15;
            *(uint4*)&xh[kk][c2 * 8] =
                *(const uint4*)(xb + (size_t)(k0 + kk) * NPIX + m0 + c2 * 8);
        }
        // W tiles: 64j x 32k fp16 hi/lo, straight copies with chunk swizzle
#pragma unroll
        for (int i = 0; i < 2; i++) {
            const int seg = i * 128 + t;
            const int jj = seg >> 2, ck = seg & 3;
            const int slot = ck ^ fsw(jj);
            const size_t go = (size_t)(j0 + jj) * CDIM + k0 + ck * 8;
            *(uint4*)&wh[jj][slot * 8] = *(const uint4*)(wsh + go);
            *(uint4*)&wl[jj][slot * 8] = *(const uint4*)(wsl + go);
        }
        __syncthreads();

        uint32_t bfh[4][4], bfl[4][4];
#pragma unroll
        for (int ji = 0; ji < 4; ji++) {
            const int row = warp_j + ji * 8 + lr;
            const int slot = lm ^ fsw(row);
            ldm_x4(bfh[ji][0], bfh[ji][1], bfh[ji][2], bfh[ji][3],
                   smem_u32(&wh[row][slot * 8]));
            ldm_x4(bfl[ji][0], bfl[ji][1], bfl[ji][2], bfl[ji][3],
                   smem_u32(&wl[row][slot * 8]));
        }
#pragma unroll
        for (int mi = 0; mi < 4; mi++) {
            const int koff = (lm >> 1) * 8 + lr;
            const int moff = warp_m + mi * 16 + (lm & 1) * 8;
            uint32_t ah0[4], ah1[4];
            ldm_x4t(ah0[0], ah0[1], ah0[2], ah0[3], smem_u32(&xh[koff][moff]));
            ldm_x4t(ah1[0], ah1[1], ah1[2], ah1[3], smem_u32(&xh[16 + koff][moff]));
#pragma unroll
            for (int ji = 0; ji < 4; ji++) {
                mma16816(acc[mi][ji], ah0, bfh[ji][0], bfh[ji][1]);
                mma16816(acc[mi][ji], ah1, bfh[ji][2], bfh[ji][3]);
                mma16816(acc[mi][ji], ah0, bfl[ji][0], bfl[ji][1]);
                mma16816(acc[mi][ji], ah1, bfl[ji][2], bfl[ji][3]);
            }
        }
        __syncthreads();
    }

#pragma unroll
    for (int mi = 0; mi < 4; mi++) {
        const int r0 = m0 + warp_m + mi * 16 + (lane >> 2);
#pragma unroll
        for (int ji = 0; ji < 4; ji++) {
            const int jg = j0 + warp_j + ji * 8 + 2 * (lane & 3);
            const int hh = jg >> 5, dd = jg & 31;
            const size_t base = (size_t)(b * HEADS + hh) * NPIX;
            const float c0 = acc[mi][ji][0], c1 = acc[mi][ji][1];
            const float c2 = acc[mi][ji][2], c3 = acc[mi][ji][3];
            __half* dst = (which == 0) ? g_q : ((which == 1) ? g_k : g_v);
            const float s = (which == 1) ? (SCALE * LOG2E) : 1.0f;
            *(__half2*)(dst + (base + r0)     * 32 + dd) = __floats2half2_rn(c0 * s, c1 * s);
            *(__half2*)(dst + (base + r0 + 8) * 32 + dd) = __floats2half2_rn(c2 * s, c3 * s);
        }
    }
}

// ---------------------------------------------------------------------------
// Kernel 2: warp-MMA flash attention (R9 shape) with ex2.approx.f16x2 softmax.
// (unchanged from R12)
// ---------------------------------------------------------------------------
#define ATT_STAGE 16384
#define ATT_BIAS  32768
#define ATT_SMEM  (ATT_BIAS + 2080 * 4)

__global__ __launch_bounds__(128) void attn_kernel(const float* __restrict__ rel_bias)
{
    extern __shared__ __align__(16) char dsm[];
    const int t = threadIdx.x, w = t >> 5, lane = t & 31;
    const int qb = blockIdx.x, h = blockIdx.y, b = blockIdx.z;
    const size_t bh = (size_t)b * HEADS + h;
    const int lr = lane & 7;
    const int lm = lane >> 3;

    // stage Q in stage-0 region (overwritten by the pipeline later)
    const __half* qg = g_q + (bh * NPIX + (size_t)qb * 128) * HEAD_DIM;
#pragma unroll
    for (int i = t; i < 512; i += 128) {
        const int r = i >> 2, c = i & 3;
        *(uint4*)(dsm + r * 128 + ((c ^ (r & 7)) * 16)) =
            *(const uint4*)(qg + r * 32 + c * 8);
    }
    float* biasS = (float*)(dsm + ATT_BIAS);
    for (int i = t; i < 2080; i += 128)
        biasS[i] = rel_bias[h * 3969 + i] * LOG2E;
    __syncthreads();

    uint32_t qf[2][2][4];
    {
        const uint32_t qbase = smem_u32(dsm);
#pragma unroll
        for (int mt = 0; mt < 2; mt++)
#pragma unroll
            for (int kc = 0; kc < 2; kc++) {
                const int row = w * 32 + mt * 16 + (lm & 1) * 8 + lr;
                const int ch  = (kc * 2 + (lm >> 1)) ^ lr;
                ldm_x4(qf[mt][kc][0], qf[mt][kc][1], qf[mt][kc][2], qf[mt][kc][3],
                       qbase + row * 128 + ch * 16);
            }
    }
    __syncthreads();

    const __half* kg = g_k + bh * NPIX * HEAD_DIM;
    const __half* vg = g_v + bh * NPIX * HEAD_DIM;

    auto load_tile = [&](int it, int st) {
        char* base = dsm + st * ATT_STAGE;
#pragma unroll
        for (int i = 0; i < 4; i++) {
            const int idx4 = i * 128 + t;
            const int arr = idx4 >> 8, idx = idx4 & 255;
            const int r = idx >> 2, c = idx & 3;
            const size_t go = (size_t)(it * 64 + r) * 32 + c * 8;
            const uint32_t so = (uint32_t)(arr * 8192 + r * 128 + ((c ^ (r & 7)) * 16));
            const __half* src = (arr == 0) ? kg : vg;
            cp16(smem_u32(base + so), src + go);
        }
    };

    load_tile(0, 0); CP_COMMIT();
    load_tile(1, 1); CP_COMMIT();

    float O[2][4][4];
#pragma unroll
    for (int mt = 0; mt < 2; mt++)
#pragma unroll
        for (int dn = 0; dn < 4; dn++)
#pragma unroll
            for (int r = 0; r < 4; r++) O[mt][dn][r] = 0.f;
    float lacc[2][2] = {{0.f, 0.f}, {0.f, 0.f}};

    const int irow0 = qb * 128 + w * 32 + (lane >> 2);
    const int bcol  = 2 * (lane & 3);

#pragma unroll 1
    for (int it = 0; it < 16; ++it) {
        if (it < 15) { CP_WAIT1(); } else { CP_WAIT0(); }
        __syncthreads();

        const char* base = dsm + (it & 1) * ATT_STAGE;
        const uint32_t kb0 = smem_u32(base);
        const uint32_t vh0 = kb0 + 8192;
        const int jt = it * 64;

#pragma unroll 1
        for (int kc = 0; kc < 4; ++kc) {
            uint32_t ph[2][4];
#pragma unroll
            for (int j2 = 0; j2 < 2; ++j2) {
                const int jn = kc * 2 + j2;
                uint32_t kbf[4];
                ldm_x4(kbf[0], kbf[1], kbf[2], kbf[3],
                       kb0 + (jn * 8 + lr) * 128 + ((lm ^ lr) * 16));
                float S0[4] = {0.f, 0.f, 0.f, 0.f};
                float S1[4] = {0.f, 0.f, 0.f, 0.f};
                mma16816(S0, qf[0][0], kbf[0], kbf[1]);
                mma16816(S0, qf[0][1], kbf[2], kbf[3]);
                mma16816(S1, qf[1][0], kbf[0], kbf[1]);
                mma16816(S1, qf[1][1], kbf[2], kbf[3]);

                const int sb2 = j2 * 2;
#pragma unroll
                for (int mt = 0; mt < 2; ++mt) {
                    const float* S = (mt == 0) ? S0 : S1;
                    const int bidx = 1056 - (irow0 + mt * 16) + jt + jn * 8 + bcol;
                    const float a0 = S[0] + biasS[bidx];
                    const float a1 = S[1] + biasS[bidx + 1];
                    const float a2 = S[2] + biasS[bidx - 8];
                    const float a3 = S[3] + biasS[bidx - 7];
                    const uint32_t p01 = ex2_f16x2(h2u(__floats2half2_rn(a0, a1)));
                    const uint32_t p23 = ex2_f16x2(h2u(__floats2half2_rn(a2, a3)));
                    ph[mt][sb2]     = p01;
                    ph[mt][sb2 + 1] = p23;
                    const float2 f01 = __half22float2(*(const __half2*)&p01);
                    const float2 f23 = __half22float2(*(const __half2*)&p23);
                    lacc[mt][0] += f01.x + f01.y;
                    lacc[mt][1] += f23.x + f23.y;
                }
            }
            const int vrow = kc * 16 + (lm & 1) * 8 + lr;
            uint32_t bvh[4][2];
            ldm_x4t(bvh[0][0], bvh[0][1], bvh[1][0], bvh[1][1],
                    vh0 + vrow * 128 + (((0 + (lm >> 1)) ^ lr) * 16));
            ldm_x4t(bvh[2][0], bvh[2][1], bvh[3][0], bvh[3][1],
                    vh0 + vrow * 128 + (((2 + (lm >> 1)) ^ lr) * 16));
#pragma unroll
            for (int mt = 0; mt < 2; ++mt)
#pragma unroll
                for (int dn = 0; dn < 4; ++dn)
                    mma16816(O[mt][dn], ph[mt], bvh[dn][0], bvh[dn][1]);
        }
        __syncthreads();
        if (it < 14) { load_tile(it + 2, it & 1); CP_COMMIT(); }
    }

    float linv[2][2];
#pragma unroll
    for (int mt = 0; mt < 2; ++mt)
#pragma unroll
        for (int rh = 0; rh < 2; ++rh) {
            float l = lacc[mt][rh];
            l += __shfl_xor_sync(0xFFFFFFFF, l, 1);
            l += __shfl_xor_sync(0xFFFFFFFF, l, 2);
            linv[mt][rh] = 1.f / l;
        }

    __half* ao = g_ao + (size_t)b * NPIX * DIM;
#pragma unroll
    for (int mt = 0; mt < 2; ++mt) {
        const int row = qb * 128 + w * 32 + mt * 16 + (lane >> 2);
#pragma unroll
        for (int dn = 0; dn < 4; ++dn) {
            const int col = h * 32 + dn * 8 + 2 * (lane & 3);
            *(__half2*)(ao + (size_t)row * DIM + col) =
                __floats2half2_rn(O[mt][dn][0] * linv[mt][0],
                                  O[mt][dn][1] * linv[mt][0]);
            *(__half2*)(ao + (size_t)(row + 8) * DIM + col) =
                __floats2half2_rn(O[mt][dn][2] * linv[mt][1],
                                  O[mt][dn][3] * linv[mt][1]);
        }
    }
}

// ---------------------------------------------------------------------------
// Kernel 3: output projection on HMMA. 2-term (Wo hi/lo, pre-converted) x Ao.
// ---------------------------------------------------------------------------
__global__ __launch_bounds__(128) void oproj_kernel(
    const float* __restrict__ bo, float* __restrict__ out)
{
    __shared__ __align__(16) __half woh[64][32];
    __shared__ __align__(16) __half wol[64][32];
    __shared__ __align__(16) __half bhs[128][32];

    const int c0 = blockIdx.x * 64;
    const int p0 = blockIdx.y * 128;
    const int b  = blockIdx.z;
    const int t = threadIdx.x, w = t >> 5, lane = t & 31;
    const int lr = lane & 7, lm = lane >> 3;
    const int warp_c = (w & 1) * 32, warp_p = (w >> 1) * 64;

    const __half* ao  = g_ao + (size_t)b * NPIX * DIM;
    const __half* wsh = g_wh + (size_t)3 * CDIM * DIM;
    const __half* wsl = g_wl + (size_t)3 * CDIM * DIM;

    float acc[2][8][4];
#pragma unroll
    for (int mi = 0; mi < 2; mi++)
#pragma unroll
        for (int ji = 0; ji < 8; ji++)
#pragma unroll
            for (int r = 0; r < 4; r++) acc[mi][ji][r] = 0.f;

    for (int k0 = 0; k0 < DIM; k0 += 32) {
        // Wo tiles: pure fp16 copies with chunk swizzle
#pragma unroll
        for (int i = 0; i < 2; i++) {
            const int seg = i * 128 + t;
            const int cc = seg >> 2, ck = seg & 3;
            const int slot = ck ^ fsw(cc);
            const size_t go = (size_t)(c0 + cc) * DIM + k0 + ck * 8;
            *(uint4*)&woh[cc][slot * 8] = *(const uint4*)(wsh + go);
            *(uint4*)&wol[cc][slot * 8] = *(const uint4*)(wsl + go);
        }
#pragma unroll
        for (int i = 0; i < 4; i++) {
            const int idx = i * 128 + t;
            const int r = idx >> 2, ck = idx & 3;
            const int slot = ck ^ fsw(r);
            const size_t go = (size_t)(p0 + r) * DIM + k0 + ck * 8;
            *(uint4*)&bhs[r][slot * 8] = *(const uint4*)(ao + go);
        }
        __syncthreads();

        uint32_t awh[2][2][4], awl[2][2][4];
#pragma unroll
        for (int mi = 0; mi < 2; mi++)
#pragma unroll
            for (int kf = 0; kf < 2; kf++) {
                const int row = warp_c + mi * 16 + (lm & 1) * 8 + lr;
                const int slot = (kf * 2 + (lm >> 1)) ^ fsw(row);
                ldm_x4(awh[mi][kf][0], awh[mi][kf][1], awh[mi][kf][2], awh[mi][kf][3],
                       smem_u32(&woh[row][slot * 8]));
                ldm_x4(awl[mi][kf][0], awl[mi][kf][1], awl[mi][kf][2], awl[mi][kf][3],
                       smem_u32(&wol[row][slot * 8]));
            }
#pragma unroll
        for (int ji = 0; ji < 8; ji++) {
            const int prow = warp_p + ji * 8 + lr;
            const int slot = lm ^ fsw(prow);
            uint32_t bbh[4];
            ldm_x4(bbh[0], bbh[1], bbh[2], bbh[3], smem_u32(&bhs[prow][slot * 8]));
#pragma unroll
            for (int mi = 0; mi < 2; mi++) {
                mma16816(acc[mi][ji], awh[mi][0], bbh[0], bbh[1]);
                mma16816(acc[mi][ji], awh[mi][1], bbh[2], bbh[3]);
                mma16816(acc[mi][ji], awl[mi][0], bbh[0], bbh[1]);
                mma16816(acc[mi][ji], awl[mi][1], bbh[2], bbh[3]);
            }
        }
        __syncthreads();
    }

#pragma unroll
    for (int mi = 0; mi < 2; mi++) {
        const int c = c0 + warp_c + mi * 16 + (lane >> 2);
        const float bias0 = __ldg(bo + c);
        const float bias1 = __ldg(bo + c + 8);
        float* o0 = out + ((size_t)b * CDIM + c) * NPIX;
        float* o1 = out + ((size_t)b * CDIM + c + 8) * NPIX;
#pragma unroll
        for (int ji = 0; ji < 8; ji++) {
            const int pix = p0 + warp_p + ji * 8 + 2 * (lane & 3);
            *(float2*)(o0 + pix) = make_float2(acc[mi][ji][0] + bias0,
                                               acc[mi][ji][1] + bias0);
            *(float2*)(o1 + pix) = make_float2(acc[mi][ji][2] + bias1,
                                               acc[mi][ji][3] + bias1);
        }
    }
}

// ---------------------------------------------------------------------------
extern "C" void kernel_launch(void* const* d_in, const int* in_sizes, int n_in,
                              void* d_out, int out_size)
{
    (void)in_sizes; (void)n_in; (void)out_size;
    const float* x        = (const float*)d_in[0];
    const float* Wq       = (const float*)d_in[1];
    const float* Wk       = (const float*)d_in[2];
    const float* Wv       = (const float*)d_in[3];
    const float* Wo       = (const float*)d_in[4];
    const float* bo       = (const float*)d_in[5];
    const float* rel_bias = (const float*)d_in[6];
    /* d_in[7] = rel_idx unused: idx(i,j) == j - i + 1056 analytically */
    float* out = (float*)d_out;

    static bool attr_done = false;
    if (!attr_done) {
        cudaFuncSetAttribute(attn_kernel,
                             cudaFuncAttributeMaxDynamicSharedMemorySize, ATT_SMEM);
        attr_done = true;
    }

    xcvt_kernel<<<(BATCH * CDIM * NPIX) / (256 * 8), 256>>>(x);
    wcvt_kernel<<<dim3((CDIM * DIM) / (256 * 8), 4), 256>>>(Wq, Wk, Wv, Wo);
    qkv_kernel<<<dim3(12, 8, 16), 128>>>();
    attn_kernel<<<dim3(8, HEADS, BATCH), 128, ATT_SMEM>>>(rel_bias);
    oproj_kernel<<<dim3(4, 8, 16), 128>>>(bo, out);
}

// round 14
// speedup vs baseline: 1.0469x; 1.0469x over previous
#include <cuda_runtime.h>
#include <cuda_fp16.h>
#include <cstdint>

#define HEADS 8
#define HEAD_DIM 32
#define NPIX 1024
#define BATCH 16
#define CDIM 256
#define DIM 256
#define SCALE 0.17677669529663687f  /* 32^-0.5 */
#define LOG2E 1.4426950408889634f
#define ONES16 0x3C003C00u          /* fp16x2 {1.0, 1.0} */

// Scratch (allocation-free rule: __device__ globals)
__device__ __half g_xh[(size_t)BATCH * CDIM * NPIX];            // fp16 copy of x
__device__ __half g_q [(size_t)BATCH * HEADS * NPIX * HEAD_DIM];
__device__ __half g_k [(size_t)BATCH * HEADS * NPIX * HEAD_DIM]; // pre-scaled SCALE*log2e
__device__ __half g_v [(size_t)BATCH * HEADS * NPIX * HEAD_DIM];
__device__ __half g_ao[(size_t)BATCH * NPIX * DIM];

// ---------------- warp-MMA helpers (base ISA, no 'a' features) ---------------
__device__ __forceinline__ uint32_t smem_u32(const void* p) {
    uint32_t a;
    asm("{ .reg .u64 t; cvta.to.shared.u64 t, %1; cvt.u32.u64 %0, t; }"
        : "=r"(a) : "l"(p));
    return a;
}
__device__ __forceinline__ void ldm_x4(uint32_t& r0, uint32_t& r1,
                                       uint32_t& r2, uint32_t& r3, uint32_t a) {
    asm volatile("ldmatrix.sync.aligned.m8n8.x4.shared.b16 {%0,%1,%2,%3}, [%4];"
                 : "=r"(r0), "=r"(r1), "=r"(r2), "=r"(r3) : "r"(a));
}
__device__ __forceinline__ void ldm_x4t(uint32_t& r0, uint32_t& r1,
                                        uint32_t& r2, uint32_t& r3, uint32_t a) {
    asm volatile("ldmatrix.sync.aligned.m8n8.x4.trans.shared.b16 {%0,%1,%2,%3}, [%4];"
                 : "=r"(r0), "=r"(r1), "=r"(r2), "=r"(r3) : "r"(a));
}
__device__ __forceinline__ void mma16816(float* d, const uint32_t* a,
                                         uint32_t b0, uint32_t b1) {
    asm volatile(
        "mma.sync.aligned.m16n8k16.row.col.f32.f16.f16.f32 "
        "{%0,%1,%2,%3}, {%4,%5,%6,%7}, {%8,%9}, {%0,%1,%2,%3};"
        : "+f"(d[0]), "+f"(d[1]), "+f"(d[2]), "+f"(d[3])
        : "r"(a[0]), "r"(a[1]), "r"(a[2]), "r"(a[3]), "r"(b0), "r"(b1));
}
__device__ __forceinline__ uint32_t h2u(__half2 h) {
    return *reinterpret_cast<uint32_t*>(&h);
}
__device__ __forceinline__ uint32_t ex2_f16x2(uint32_t x) {
    uint32_t r;
    asm("ex2.approx.f16x2 %0, %1;" : "=r"(r) : "r"(x));
    return r;
}
__device__ __forceinline__ void split4(const float4 v,
                                       uint32_t& h01, uint32_t& h23,
                                       uint32_t& l01, uint32_t& l23) {
    const __half2 a = __floats2half2_rn(v.x, v.y);
    const __half2 b = __floats2half2_rn(v.z, v.w);
    const float2 fa = __half22float2(a);
    const float2 fb = __half22float2(b);
    h01 = h2u(a); h23 = h2u(b);
    l01 = h2u(__floats2half2_rn(v.x - fa.x, v.y - fa.y));
    l23 = h2u(__floats2half2_rn(v.z - fb.x, v.w - fb.y));
}
__device__ __forceinline__ int fsw(int row) { return (row ^ (row >> 2)) & 3; }

// cp.async (base ISA since sm_80)
__device__ __forceinline__ void cp16(uint32_t dst, const void* src) {
    asm volatile("cp.async.cg.shared.global [%0], [%1], 16;"
                 :: "r"(dst), "l"(src));
}
#define CP_COMMIT() asm volatile("cp.async.commit_group;" ::: "memory")
#define CP_WAIT1()  asm volatile("cp.async.wait_group 1;" ::: "memory")
#define CP_WAIT0()  asm volatile("cp.async.wait_group 0;" ::: "memory")

// ---------------------------------------------------------------------------
// Kernel 0: one-shot x fp32 -> fp16.
// ---------------------------------------------------------------------------
__global__ __launch_bounds__(256) void xcvt_kernel(const float* __restrict__ x)
{
    const size_t i = ((size_t)blockIdx.x * 256 + threadIdx.x) * 8;
    const float4 a = *(const float4*)(x + i);
    const float4 b = *(const float4*)(x + i + 4);
    uint4 o;
    o.x = h2u(__floats2half2_rn(a.x, a.y));
    o.y = h2u(__floats2half2_rn(a.z, a.w));
    o.z = h2u(__floats2half2_rn(b.x, b.y));
    o.w = h2u(__floats2half2_rn(b.z, b.w));
    *(uint4*)(g_xh + i) = o;
}

// ---------------------------------------------------------------------------
// Kernel 1: fused QKV projection on HMMA (R12 shape), 2-term: x_h*(W_h+W_l).
// ---------------------------------------------------------------------------
__global__ __launch_bounds__(128) void qkv_kernel(
    const float* __restrict__ Wq, const float* __restrict__ Wk,
    const float* __restrict__ Wv)
{
    __shared__ __align__(16) __half xh[32][136];   // [k][m], padded rows
    __shared__ __align__(16) __half wh[64][32];    // [j][k], chunk-swizzled
    __shared__ __align__(16) __half wl[64][32];

    const int nt = blockIdx.x;          // 0..11
    const int which = nt >> 2;          // 0=Q, 1=K, 2=V
    const int j0 = (nt & 3) * 64;
    const int m0 = blockIdx.y * 128;
    const int b  = blockIdx.z;
    const float* W = (which == 0) ? Wq : ((which == 1) ? Wk : Wv);
    const __half* xb = g_xh + (size_t)b * CDIM * NPIX;

    const int t = threadIdx.x, w = t >> 5, lane = t & 31;
    const int lr = lane & 7, lm = lane >> 3;
    const int warp_m = (w & 1) * 64, warp_j = (w >> 1) * 32;

    float acc[4][4][4];
#pragma unroll
    for (int mi = 0; mi < 4; mi++)
#pragma unroll
        for (int ji = 0; ji < 4; ji++)
#pragma unroll
            for (int r = 0; r < 4; r++) acc[mi][ji][r] = 0.f;

    for (int k0 = 0; k0 < CDIM; k0 += 32) {
        // x tile: 32k x 128m fp16, straight 16B copies
#pragma unroll
        for (int i = 0; i < 4; i++) {
            const int idx = i * 128 + t;
            const int kk = idx >> 4, c2 = idx & 15;
            *(uint4*)&xh[kk][c2 * 8] =
                *(const uint4*)(xb + (size_t)(k0 + kk) * NPIX + m0 + c2 * 8);
        }
        // W tile: 64j x 32k fp32 -> hi/lo, 16B-chunk swizzle per row
#pragma unroll
        for (int i = 0; i < 2; i++) {
            const int seg = i * 128 + t;
            const int jj = seg >> 2, ck = seg & 3;
            const float* src = W + (size_t)(j0 + jj) * CDIM + k0 + ck * 8;
            const float4 a = *(const float4*)(src);
            const float4 c = *(const float4*)(src + 4);
            uint4 uh, ul;
            split4(a, uh.x, uh.y, ul.x, ul.y);
            split4(c, uh.z, uh.w, ul.z, ul.w);
            const int slot = ck ^ fsw(jj);
            *(uint4*)&wh[jj][slot * 8] = uh;
            *(uint4*)&wl[jj][slot * 8] = ul;
        }
        __syncthreads();

        uint32_t bfh[4][4], bfl[4][4];
#pragma unroll
        for (int ji = 0; ji < 4; ji++) {
            const int row = warp_j + ji * 8 + lr;
            const int slot = lm ^ fsw(row);
            ldm_x4(bfh[ji][0], bfh[ji][1], bfh[ji][2], bfh[ji][3],
                   smem_u32(&wh[row][slot * 8]));
            ldm_x4(bfl[ji][0], bfl[ji][1], bfl[ji][2], bfl[ji][3],
                   smem_u32(&wl[row][slot * 8]));
        }
#pragma unroll
        for (int mi = 0; mi < 4; mi++) {
            const int koff = (lm >> 1) * 8 + lr;
            const int moff = warp_m + mi * 16 + (lm & 1) * 8;
            uint32_t ah0[4], ah1[4];
            ldm_x4t(ah0[0], ah0[1], ah0[2], ah0[3], smem_u32(&xh[koff][moff]));
            ldm_x4t(ah1[0], ah1[1], ah1[2], ah1[3], smem_u32(&xh[16 + koff][moff]));
#pragma unroll
            for (int ji = 0; ji < 4; ji++) {
                mma16816(acc[mi][ji], ah0, bfh[ji][0], bfh[ji][1]);
                mma16816(acc[mi][ji], ah1, bfh[ji][2], bfh[ji][3]);
                mma16816(acc[mi][ji], ah0, bfl[ji][0], bfl[ji][1]);
                mma16816(acc[mi][ji], ah1, bfl[ji][2], bfl[ji][3]);
            }
        }
        __syncthreads();
    }

#pragma unroll
    for (int mi = 0; mi < 4; mi++) {
        const int r0 = m0 + warp_m + mi * 16 + (lane >> 2);
#pragma unroll
        for (int ji = 0; ji < 4; ji++) {
            const int jg = j0 + warp_j + ji * 8 + 2 * (lane & 3);
            const int hh = jg >> 5, dd = jg & 31;
            const size_t base = (size_t)(b * HEADS + hh) * NPIX;
            const float c0 = acc[mi][ji][0], c1 = acc[mi][ji][1];
            const float c2 = acc[mi][ji][2], c3 = acc[mi][ji][3];
            __half* dst = (which == 0) ? g_q : ((which == 1) ? g_k : g_v);
            const float s = (which == 1) ? (SCALE * LOG2E) : 1.0f;
            *(__half2*)(dst + (base + r0)     * 32 + dd) = __floats2half2_rn(c0 * s, c1 * s);
            *(__half2*)(dst + (base + r0 + 8) * 32 + dd) = __floats2half2_rn(c2 * s, c3 * s);
        }
    }
}

// ---------------------------------------------------------------------------
// Kernel 2: warp-MMA flash attention, ex2.f16x2 softmax, and the softmax
// denominator computed ON THE TENSOR PIPE: l = P x ones via one extra MMA
// per chunk. C-fragment row-broadcast means no shuffles in the epilogue.
// ---------------------------------------------------------------------------
#define ATT_STAGE 16384
#define ATT_BIAS  32768
#define ATT_SMEM  (ATT_BIAS + 2080 * 4)

__global__ __launch_bounds__(128) void attn_kernel(const float* __restrict__ rel_bias)
{
    extern __shared__ __align__(16) char dsm[];
    const int t = threadIdx.x, w = t >> 5, lane = t & 31;
    const int qb = blockIdx.x, h = blockIdx.y, b = blockIdx.z;
    const size_t bh = (size_t)b * HEADS + h;
    const int lr = lane & 7;
    const int lm = lane >> 3;

    // stage Q in stage-0 region (overwritten by the pipeline later)
    const __half* qg = g_q + (bh * NPIX + (size_t)qb * 128) * HEAD_DIM;
#pragma unroll
    for (int i = t; i < 512; i += 128) {
        const int r = i >> 2, c = i & 3;
        *(uint4*)(dsm + r * 128 + ((c ^ (r & 7)) * 16)) =
            *(const uint4*)(qg + r * 32 + c * 8);
    }
    float* biasS = (float*)(dsm + ATT_BIAS);
    for (int i = t; i < 2080; i += 128)
        biasS[i] = rel_bias[h * 3969 + i] * LOG2E;
    __syncthreads();

    uint32_t qf[2][2][4];
    {
        const uint32_t qbase = smem_u32(dsm);
#pragma unroll
        for (int mt = 0; mt < 2; mt++)
#pragma unroll
            for (int kc = 0; kc < 2; kc++) {
                const int row = w * 32 + mt * 16 + (lm & 1) * 8 + lr;
                const int ch  = (kc * 2 + (lm >> 1)) ^ lr;
                ldm_x4(qf[mt][kc][0], qf[mt][kc][1], qf[mt][kc][2], qf[mt][kc][3],
                       qbase + row * 128 + ch * 16);
            }
    }
    __syncthreads();

    const __half* kg = g_k + bh * NPIX * HEAD_DIM;
    const __half* vg = g_v + bh * NPIX * HEAD_DIM;

    auto load_tile = [&](int it, int st) {
        char* base = dsm + st * ATT_STAGE;
#pragma unroll
        for (int i = 0; i < 4; i++) {
            const int idx4 = i * 128 + t;
            const int arr = idx4 >> 8, idx = idx4 & 255;
            const int r = idx >> 2, c = idx & 3;
            const size_t go = (size_t)(it * 64 + r) * 32 + c * 8;
            const uint32_t so = (uint32_t)(arr * 8192 + r * 128 + ((c ^ (r & 7)) * 16));
            const __half* src = (arr == 0) ? kg : vg;
            cp16(smem_u32(base + so), src + go);
        }
    };

    load_tile(0, 0); CP_COMMIT();
    load_tile(1, 1); CP_COMMIT();

    float O[2][4][4];
#pragma unroll
    for (int mt = 0; mt < 2; mt++)
#pragma unroll
        for (int dn = 0; dn < 4; dn++)
#pragma unroll
            for (int r = 0; r < 4; r++) O[mt][dn][r] = 0.f;
    float laccF[2][4];
#pragma unroll
    for (int mt = 0; mt < 2; mt++)
#pragma unroll
        for (int r = 0; r < 4; r++) laccF[mt][r] = 0.f;

    const int irow0 = qb * 128 + w * 32 + (lane >> 2);
    const int bcol  = 2 * (lane & 3);

#pragma unroll 1
    for (int it = 0; it < 16; ++it) {
        if (it < 15) { CP_WAIT1(); } else { CP_WAIT0(); }
        __syncthreads();

        const char* base = dsm + (it & 1) * ATT_STAGE;
        const uint32_t kb0 = smem_u32(base);
        const uint32_t vh0 = kb0 + 8192;
        const int jt = it * 64;

#pragma unroll 1
        for (int kc = 0; kc < 4; ++kc) {
            uint32_t ph[2][4];
#pragma unroll
            for (int j2 = 0; j2 < 2; ++j2) {
                const int jn = kc * 2 + j2;
                uint32_t kbf[4];
                ldm_x4(kbf[0], kbf[1], kbf[2], kbf[3],
                       kb0 + (jn * 8 + lr) * 128 + ((lm ^ lr) * 16));
                float S0[4] = {0.f, 0.f, 0.f, 0.f};
                float S1[4] = {0.f, 0.f, 0.f, 0.f};
                mma16816(S0, qf[0][0], kbf[0], kbf[1]);
                mma16816(S0, qf[0][1], kbf[2], kbf[3]);
                mma16816(S1, qf[1][0], kbf[0], kbf[1]);
                mma16816(S1, qf[1][1], kbf[2], kbf[3]);

                const int sb2 = j2 * 2;
#pragma unroll
                for (int mt = 0; mt < 2; ++mt) {
                    const float* S = (mt == 0) ? S0 : S1;
                    const int bidx = 1056 - (irow0 + mt * 16) + jt + jn * 8 + bcol;
                    const float a0 = S[0] + biasS[bidx];
                    const float a1 = S[1] + biasS[bidx + 1];
                    const float a2 = S[2] + biasS[bidx - 8];
                    const float a3 = S[3] + biasS[bidx - 7];
                    ph[mt][sb2]     = ex2_f16x2(h2u(__floats2half2_rn(a0, a1)));
                    ph[mt][sb2 + 1] = ex2_f16x2(h2u(__floats2half2_rn(a2, a3)));
                }
            }
            // PV + row-sum (denominator) for this 16-key chunk, all on tensor pipe
            const int vrow = kc * 16 + (lm & 1) * 8 + lr;
            uint32_t bvh[4][2];
            ldm_x4t(bvh[0][0], bvh[0][1], bvh[1][0], bvh[1][1],
                    vh0 + vrow * 128 + (((0 + (lm >> 1)) ^ lr) * 16));
            ldm_x4t(bvh[2][0], bvh[2][1], bvh[3][0], bvh[3][1],
                    vh0 + vrow * 128 + (((2 + (lm >> 1)) ^ lr) * 16));
#pragma unroll
            for (int mt = 0; mt < 2; ++mt) {
                mma16816(laccF[mt], ph[mt], ONES16, ONES16);
#pragma unroll
                for (int dn = 0; dn < 4; ++dn)
                    mma16816(O[mt][dn], ph[mt], bvh[dn][0], bvh[dn][1]);
            }
        }
        __syncthreads();
        if (it < 14) { load_tile(it + 2, it & 1); CP_COMMIT(); }
    }

    // laccF[mt][0] = row sum (rows lane>>2), laccF[mt][2] = rows +8. No shuffles.
    __half* ao = g_ao + (size_t)b * NPIX * DIM;
#pragma unroll
    for (int mt = 0; mt < 2; ++mt) {
        const float li0 = 1.f / laccF[mt][0];
        const float li1 = 1.f / laccF[mt][2];
        const int row = qb * 128 + w * 32 + mt * 16 + (lane >> 2);
#pragma unroll
        for (int dn = 0; dn < 4; ++dn) {
            const int col = h * 32 + dn * 8 + 2 * (lane & 3);
            *(__half2*)(ao + (size_t)row * DIM + col) =
                __floats2half2_rn(O[mt][dn][0] * li0, O[mt][dn][1] * li0);
            *(__half2*)(ao + (size_t)(row + 8) * DIM + col) =
                __floats2half2_rn(O[mt][dn][2] * li1, O[mt][dn][3] * li1);
        }
    }
}

// ---------------------------------------------------------------------------
// Kernel 3: output projection on HMMA (R12 shape). 2-term (Wo hi/lo) x Ao.
// ---------------------------------------------------------------------------
__global__ __launch_bounds__(128) void oproj_kernel(
    const float* __restrict__ Wo, const float* __restrict__ bo,
    float* __restrict__ out)
{
    __shared__ __align__(16) __half woh[64][32];
    __shared__ __align__(16) __half wol[64][32];
    __shared__ __align__(16) __half bhs[128][32];

    const int c0 = blockIdx.x * 64;
    const int p0 = blockIdx.y * 128;
    const int b  = blockIdx.z;
    const int t = threadIdx.x, w = t >> 5, lane = t & 31;
    const int lr = lane & 7, lm = lane >> 3;
    const int warp_c = (w & 1) * 32, warp_p = (w >> 1) * 64;

    const __half* ao = g_ao + (size_t)b * NPIX * DIM;

    float acc[2][8][4];
#pragma unroll
    for (int mi = 0; mi < 2; mi++)
#pragma unroll
        for (int ji = 0; ji < 8; ji++)
#pragma unroll
            for (int r = 0; r < 4; r++) acc[mi][ji][r] = 0.f;

    for (int k0 = 0; k0 < DIM; k0 += 32) {
#pragma unroll
        for (int i = 0; i < 2; i++) {
            const int seg = i * 128 + t;
            const int cc = seg >> 2, ck = seg & 3;
            const float* src = Wo + (size_t)(c0 + cc) * DIM + k0 + ck * 8;
            const float4 a = *(const float4*)(src);
            const float4 c = *(const float4*)(src + 4);
            uint4 uh, ul;
            split4(a, uh.x, uh.y, ul.x, ul.y);
            split4(c, uh.z, uh.w, ul.z, ul.w);
            const int slot = ck ^ fsw(cc);
            *(uint4*)&woh[cc][slot * 8] = uh;
            *(uint4*)&wol[cc][slot * 8] = ul;
        }
#pragma unroll
        for (int i = 0; i < 4; i++) {
            const int idx = i * 128 + t;
            const int r = idx >> 2, ck = idx & 3;
            const int slot = ck ^ fsw(r);
            const size_t go = (size_t)(p0 + r) * DIM + k0 + ck * 8;
            *(uint4*)&bhs[r][slot * 8] = *(const uint4*)(ao + go);
        }
        __syncthreads();

        uint32_t awh[2][2][4], awl[2][2][4];
#pragma unroll
        for (int mi = 0; mi < 2; mi++)
#pragma unroll
            for (int kf = 0; kf < 2; kf++) {
                const int row = warp_c + mi * 16 + (lm & 1) * 8 + lr;
                const int slot = (kf * 2 + (lm >> 1)) ^ fsw(row);
                ldm_x4(awh[mi][kf][0], awh[mi][kf][1], awh[mi][kf][2], awh[mi][kf][3],
                       smem_u32(&woh[row][slot * 8]));
                ldm_x4(awl[mi][kf][0], awl[mi][kf][1], awl[mi][kf][2], awl[mi][kf][3],
                       smem_u32(&wol[row][slot * 8]));
            }
#pragma unroll
        for (int ji = 0; ji < 8; ji++) {
            const int prow = warp_p + ji * 8 + lr;
            const int slot = lm ^ fsw(prow);
            uint32_t bbh[4];
            ldm_x4(bbh[0], bbh[1], bbh[2], bbh[3], smem_u32(&bhs[prow][slot * 8]));
#pragma unroll
            for (int mi = 0; mi < 2; mi++) {
                mma16816(acc[mi][ji], awh[mi][0], bbh[0], bbh[1]);
                mma16816(acc[mi][ji], awh[mi][1], bbh[2], bbh[3]);
                mma16816(acc[mi][ji], awl[mi][0], bbh[0], bbh[1]);
                mma16816(acc[mi][ji], awl[mi][1], bbh[2], bbh[3]);
            }
        }
        __syncthreads();
    }

#pragma unroll
    for (int mi = 0; mi < 2; mi++) {
        const int c = c0 + warp_c + mi * 16 + (lane >> 2);
        const float bias0 = __ldg(bo + c);
        const float bias1 = __ldg(bo + c + 8);
        float* o0 = out + ((size_t)b * CDIM + c) * NPIX;
        float* o1 = out + ((size_t)b * CDIM + c + 8) * NPIX;
#pragma unroll
        for (int ji = 0; ji < 8; ji++) {
            const int pix = p0 + warp_p + ji * 8 + 2 * (lane & 3);
            *(float2*)(o0 + pix) = make_float2(acc[mi][ji][0] + bias0,
                                               acc[mi][ji][1] + bias0);
            *(float2*)(o1 + pix) = make_float2(acc[mi][ji][2] + bias1,
                                               acc[mi][ji][3] + bias1);
        }
    }
}

// ---------------------------------------------------------------------------
extern "C" void kernel_launch(void* const* d_in, const int* in_sizes, int n_in,
                              void* d_out, int out_size)
{
    (void)in_sizes; (void)n_in; (void)out_size;
    const float* x        = (const float*)d_in[0];
    const float* Wq       = (const float*)d_in[1];
    const float* Wk       = (const float*)d_in[2];
    const float* Wv       = (const float*)d_in[3];
    const float* Wo       = (const float*)d_in[4];
    const float* bo       = (const float*)d_in[5];
    const float* rel_bias = (const float*)d_in[6];
    /* d_in[7] = rel_idx unused: idx(i,j) == j - i + 1056 analytically */
    float* out = (float*)d_out;

    static bool attr_done = false;
    if (!attr_done) {
        cudaFuncSetAttribute(attn_kernel,
                             cudaFuncAttributeMaxDynamicSharedMemorySize, ATT_SMEM);
        attr_done = true;
    }

    xcvt_kernel<<<(BATCH * CDIM * NPIX) / (256 * 8), 256>>>(x);
    qkv_kernel<<<dim3(12, 8, 16), 128>>>(Wq, Wk, Wv);
    attn_kernel<<<dim3(8, HEADS, BATCH), 128, ATT_SMEM>>>(rel_bias);
    oproj_kernel<<<dim3(4, 8, 16), 128>>>(Wo, bo, out);
}

// round 15
// speedup vs baseline: 1.1136x; 1.0636x over previous
#include <cuda_runtime.h>
#include <cuda_fp16.h>
#include <cstdint>

#define HEADS 8
#define HEAD_DIM 32
#define NPIX 1024
#define BATCH 16
#define CDIM 256
#define DIM 256
#define SCALE 0.17677669529663687f  /* 32^-0.5 */
#define LOG2E 1.4426950408889634f
#define ONES16 0x3C003C00u          /* fp16x2 {1.0, 1.0} */

// Scratch (allocation-free rule: __device__ globals)
__device__ __half g_xh[(size_t)BATCH * CDIM * NPIX];            // fp16 copy of x
__device__ __half g_q [(size_t)BATCH * HEADS * NPIX * HEAD_DIM];
__device__ __half g_k [(size_t)BATCH * HEADS * NPIX * HEAD_DIM]; // pre-scaled SCALE*log2e
__device__ __half g_v [(size_t)BATCH * HEADS * NPIX * HEAD_DIM];
__device__ __half g_ao[(size_t)BATCH * NPIX * DIM];

// ---------------- warp-MMA helpers (base ISA, no 'a' features) ---------------
__device__ __forceinline__ uint32_t smem_u32(const void* p) {
    uint32_t a;
    asm("{ .reg .u64 t; cvta.to.shared.u64 t, %1; cvt.u32.u64 %0, t; }"
        : "=r"(a) : "l"(p));
    return a;
}
__device__ __forceinline__ void ldm_x4(uint32_t& r0, uint32_t& r1,
                                       uint32_t& r2, uint32_t& r3, uint32_t a) {
    asm volatile("ldmatrix.sync.aligned.m8n8.x4.shared.b16 {%0,%1,%2,%3}, [%4];"
                 : "=r"(r0), "=r"(r1), "=r"(r2), "=r"(r3) : "r"(a));
}
__device__ __forceinline__ void ldm_x4t(uint32_t& r0, uint32_t& r1,
                                        uint32_t& r2, uint32_t& r3, uint32_t a) {
    asm volatile("ldmatrix.sync.aligned.m8n8.x4.trans.shared.b16 {%0,%1,%2,%3}, [%4];"
                 : "=r"(r0), "=r"(r1), "=r"(r2), "=r"(r3) : "r"(a));
}
__device__ __forceinline__ void mma16816(float* d, const uint32_t* a,
                                         uint32_t b0, uint32_t b1) {
    asm volatile(
        "mma.sync.aligned.m16n8k16.row.col.f32.f16.f16.f32 "
        "{%0,%1,%2,%3}, {%4,%5,%6,%7}, {%8,%9}, {%0,%1,%2,%3};"
        : "+f"(d[0]), "+f"(d[1]), "+f"(d[2]), "+f"(d[3])
        : "r"(a[0]), "r"(a[1]), "r"(a[2]), "r"(a[3]), "r"(b0), "r"(b1));
}
__device__ __forceinline__ uint32_t h2u(__half2 h) {
    return *reinterpret_cast<uint32_t*>(&h);
}
__device__ __forceinline__ uint32_t ex2_f16x2(uint32_t x) {
    uint32_t r;
    asm("ex2.approx.f16x2 %0, %1;" : "=r"(r) : "r"(x));
    return r;
}
__device__ __forceinline__ int fsw(int row) { return (row ^ (row >> 2)) & 3; }

// cp.async (base ISA since sm_80)
__device__ __forceinline__ void cp16(uint32_t dst, const void* src) {
    asm volatile("cp.async.cg.shared.global [%0], [%1], 16;"
                 :: "r"(dst), "l"(src));
}
#define CP_COMMIT() asm volatile("cp.async.commit_group;" ::: "memory")
#define CP_WAIT1()  asm volatile("cp.async.wait_group 1;" ::: "memory")
#define CP_WAIT0()  asm volatile("cp.async.wait_group 0;" ::: "memory")

// ---------------------------------------------------------------------------
// Kernel 0: one-shot x fp32 -> fp16.
// ---------------------------------------------------------------------------
__global__ __launch_bounds__(256) void xcvt_kernel(const float* __restrict__ x)
{
    const size_t i = ((size_t)blockIdx.x * 256 + threadIdx.x) * 8;
    const float4 a = *(const float4*)(x + i);
    const float4 b = *(const float4*)(x + i + 4);
    uint4 o;
    o.x = h2u(__floats2half2_rn(a.x, a.y));
    o.y = h2u(__floats2half2_rn(a.z, a.w));
    o.z = h2u(__floats2half2_rn(b.x, b.y));
    o.w = h2u(__floats2half2_rn(b.z, b.w));
    *(uint4*)(g_xh + i) = o;
}

// ---------------------------------------------------------------------------
// Kernel 1: fused QKV projection on HMMA, pure fp16 (single-term x_h * W_h).
// ---------------------------------------------------------------------------
__global__ __launch_bounds__(128) void qkv_kernel(
    const float* __restrict__ Wq, const float* __restrict__ Wk,
    const float* __restrict__ Wv)
{
    __shared__ __align__(16) __half xh[32][136];   // [k][m], padded rows
    __shared__ __align__(16) __half wh[64][32];    // [j][k], chunk-swizzled

    const int nt = blockIdx.x;          // 0..11
    const int which = nt >> 2;          // 0=Q, 1=K, 2=V
    const int j0 = (nt & 3) * 64;
    const int m0 = blockIdx.y * 128;
    const int b  = blockIdx.z;
    const float* W = (which == 0) ? Wq : ((which == 1) ? Wk : Wv);
    const __half* xb = g_xh + (size_t)b * CDIM * NPIX;

    const int t = threadIdx.x, w = t >> 5, lane = t & 31;
    const int lr = lane & 7, lm = lane >> 3;
    const int warp_m = (w & 1) * 64, warp_j = (w >> 1) * 32;

    float acc[4][4][4];
#pragma unroll
    for (int mi = 0; mi < 4; mi++)
#pragma unroll
        for (int ji = 0; ji < 4; ji++)
#pragma unroll
            for (int r = 0; r < 4; r++) acc[mi][ji][r] = 0.f;

    for (int k0 = 0; k0 < CDIM; k0 += 32) {
        // x tile: 32k x 128m fp16, straight 16B copies
#pragma unroll
        for (int i = 0; i < 4; i++) {
            const int idx = i * 128 + t;
            const int kk = idx >> 4, c2 = idx & 15;
            *(uint4*)&xh[kk][c2 * 8] =
                *(const uint4*)(xb + (size_t)(k0 + kk) * NPIX + m0 + c2 * 8);
        }
        // W tile: 64j x 32k fp32 -> fp16 hi, 16B-chunk swizzle per row
#pragma unroll
        for (int i = 0; i < 2; i++) {
            const int seg = i * 128 + t;
            const int jj = seg >> 2, ck = seg & 3;
            const float* src = W + (size_t)(j0 + jj) * CDIM + k0 + ck * 8;
            const float4 a = *(const float4*)(src);
            const float4 c = *(const float4*)(src + 4);
            uint4 uh;
            uh.x = h2u(__floats2half2_rn(a.x, a.y));
            uh.y = h2u(__floats2half2_rn(a.z, a.w));
            uh.z = h2u(__floats2half2_rn(c.x, c.y));
            uh.w = h2u(__floats2half2_rn(c.z, c.w));
            const int slot = ck ^ fsw(jj);
            *(uint4*)&wh[jj][slot * 8] = uh;
        }
        __syncthreads();

        uint32_t bfh[4][4];
#pragma unroll
        for (int ji = 0; ji < 4; ji++) {
            const int row = warp_j + ji * 8 + lr;
            const int slot = lm ^ fsw(row);
            ldm_x4(bfh[ji][0], bfh[ji][1], bfh[ji][2], bfh[ji][3],
                   smem_u32(&wh[row][slot * 8]));
        }
#pragma unroll
        for (int mi = 0; mi < 4; mi++) {
            const int koff = (lm >> 1) * 8 + lr;
            const int moff = warp_m + mi * 16 + (lm & 1) * 8;
            uint32_t ah0[4], ah1[4];
            ldm_x4t(ah0[0], ah0[1], ah0[2], ah0[3], smem_u32(&xh[koff][moff]));
            ldm_x4t(ah1[0], ah1[1], ah1[2], ah1[3], smem_u32(&xh[16 + koff][moff]));
#pragma unroll
            for (int ji = 0; ji < 4; ji++) {
                mma16816(acc[mi][ji], ah0, bfh[ji][0], bfh[ji][1]);
                mma16816(acc[mi][ji], ah1, bfh[ji][2], bfh[ji][3]);
            }
        }
        __syncthreads();
    }

#pragma unroll
    for (int mi = 0; mi < 4; mi++) {
        const int r0 = m0 + warp_m + mi * 16 + (lane >> 2);
#pragma unroll
        for (int ji = 0; ji < 4; ji++) {
            const int jg = j0 + warp_j + ji * 8 + 2 * (lane & 3);
            const int hh = jg >> 5, dd = jg & 31;
            const size_t base = (size_t)(b * HEADS + hh) * NPIX;
            const float c0 = acc[mi][ji][0], c1 = acc[mi][ji][1];
            const float c2 = acc[mi][ji][2], c3 = acc[mi][ji][3];
            __half* dst = (which == 0) ? g_q : ((which == 1) ? g_k : g_v);
            const float s = (which == 1) ? (SCALE * LOG2E) : 1.0f;
            *(__half2*)(dst + (base + r0)     * 32 + dd) = __floats2half2_rn(c0 * s, c1 * s);
            *(__half2*)(dst + (base + r0 + 8) * 32 + dd) = __floats2half2_rn(c2 * s, c3 * s);
        }
    }
}

// ---------------------------------------------------------------------------
// Kernel 2: warp-MMA flash attention (unchanged from R14): ex2.f16x2 softmax,
// denominator on tensor pipe (P x ones), fp16 O output.
// ---------------------------------------------------------------------------
#define ATT_STAGE 16384
#define ATT_BIAS  32768
#define ATT_SMEM  (ATT_BIAS + 2080 * 4)

__global__ __launch_bounds__(128) void attn_kernel(const float* __restrict__ rel_bias)
{
    extern __shared__ __align__(16) char dsm[];
    const int t = threadIdx.x, w = t >> 5, lane = t & 31;
    const int qb = blockIdx.x, h = blockIdx.y, b = blockIdx.z;
    const size_t bh = (size_t)b * HEADS + h;
    const int lr = lane & 7;
    const int lm = lane >> 3;

    // stage Q in stage-0 region (overwritten by the pipeline later)
    const __half* qg = g_q + (bh * NPIX + (size_t)qb * 128) * HEAD_DIM;
#pragma unroll
    for (int i = t; i < 512; i += 128) {
        const int r = i >> 2, c = i & 3;
        *(uint4*)(dsm + r * 128 + ((c ^ (r & 7)) * 16)) =
            *(const uint4*)(qg + r * 32 + c * 8);
    }
    float* biasS = (float*)(dsm + ATT_BIAS);
    for (int i = t; i < 2080; i += 128)
        biasS[i] = rel_bias[h * 3969 + i] * LOG2E;
    __syncthreads();

    uint32_t qf[2][2][4];
    {
        const uint32_t qbase = smem_u32(dsm);
#pragma unroll
        for (int mt = 0; mt < 2; mt++)
#pragma unroll
            for (int kc = 0; kc < 2; kc++) {
                const int row = w * 32 + mt * 16 + (lm & 1) * 8 + lr;
                const int ch  = (kc * 2 + (lm >> 1)) ^ lr;
                ldm_x4(qf[mt][kc][0], qf[mt][kc][1], qf[mt][kc][2], qf[mt][kc][3],
                       qbase + row * 128 + ch * 16);
            }
    }
    __syncthreads();

    const __half* kg = g_k + bh * NPIX * HEAD_DIM;
    const __half* vg = g_v + bh * NPIX * HEAD_DIM;

    auto load_tile = [&](int it, int st) {
        char* base = dsm + st * ATT_STAGE;
#pragma unroll
        for (int i = 0; i < 4; i++) {
            const int idx4 = i * 128 + t;
            const int arr = idx4 >> 8, idx = idx4 & 255;
            const int r = idx >> 2, c = idx & 3;
            const size_t go = (size_t)(it * 64 + r) * 32 + c * 8;
            const uint32_t so = (uint32_t)(arr * 8192 + r * 128 + ((c ^ (r & 7)) * 16));
            const __half* src = (arr == 0) ? kg : vg;
            cp16(smem_u32(base + so), src + go);
        }
    };

    load_tile(0, 0); CP_COMMIT();
    load_tile(1, 1); CP_COMMIT();

    float O[2][4][4];
#pragma unroll
    for (int mt = 0; mt < 2; mt++)
#pragma unroll
        for (int dn = 0; dn < 4; dn++)
#pragma unroll
            for (int r = 0; r < 4; r++) O[mt][dn][r] = 0.f;
    float laccF[2][4];
#pragma unroll
    for (int mt = 0; mt < 2; mt++)
#pragma unroll
        for (int r = 0; r < 4; r++) laccF[mt][r] = 0.f;

    const int irow0 = qb * 128 + w * 32 + (lane >> 2);
    const int bcol  = 2 * (lane & 3);

#pragma unroll 1
    for (int it = 0; it < 16; ++it) {
        if (it < 15) { CP_WAIT1(); } else { CP_WAIT0(); }
        __syncthreads();

        const char* base = dsm + (it & 1) * ATT_STAGE;
        const uint32_t kb0 = smem_u32(base);
        const uint32_t vh0 = kb0 + 8192;
        const int jt = it * 64;

#pragma unroll 1
        for (int kc = 0; kc < 4; ++kc) {
            uint32_t ph[2][4];
#pragma unroll
            for (int j2 = 0; j2 < 2; ++j2) {
                const int jn = kc * 2 + j2;
                uint32_t kbf[4];
                ldm_x4(kbf[0], kbf[1], kbf[2], kbf[3],
                       kb0 + (jn * 8 + lr) * 128 + ((lm ^ lr) * 16));
                float S0[4] = {0.f, 0.f, 0.f, 0.f};
                float S1[4] = {0.f, 0.f, 0.f, 0.f};
                mma16816(S0, qf[0][0], kbf[0], kbf[1]);
                mma16816(S0, qf[0][1], kbf[2], kbf[3]);
                mma16816(S1, qf[1][0], kbf[0], kbf[1]);
                mma16816(S1, qf[1][1], kbf[2], kbf[3]);

                const int sb2 = j2 * 2;
#pragma unroll
                for (int mt = 0; mt < 2; ++mt) {
                    const float* S = (mt == 0) ? S0 : S1;
                    const int bidx = 1056 - (irow0 + mt * 16) + jt + jn * 8 + bcol;
                    const float a0 = S[0] + biasS[bidx];
                    const float a1 = S[1] + biasS[bidx + 1];
                    const float a2 = S[2] + biasS[bidx - 8];
                    const float a3 = S[3] + biasS[bidx - 7];
                    ph[mt][sb2]     = ex2_f16x2(h2u(__floats2half2_rn(a0, a1)));
                    ph[mt][sb2 + 1] = ex2_f16x2(h2u(__floats2half2_rn(a2, a3)));
                }
            }
            // PV + row-sum (denominator) for this 16-key chunk, all on tensor pipe
            const int vrow = kc * 16 + (lm & 1) * 8 + lr;
            uint32_t bvh[4][2];
            ldm_x4t(bvh[0][0], bvh[0][1], bvh[1][0], bvh[1][1],
                    vh0 + vrow * 128 + (((0 + (lm >> 1)) ^ lr) * 16));
            ldm_x4t(bvh[2][0], bvh[2][1], bvh[3][0], bvh[3][1],
                    vh0 + vrow * 128 + (((2 + (lm >> 1)) ^ lr) * 16));
#pragma unroll
            for (int mt = 0; mt < 2; ++mt) {
                mma16816(laccF[mt], ph[mt], ONES16, ONES16);
#pragma unroll
                for (int dn = 0; dn < 4; ++dn)
                    mma16816(O[mt][dn], ph[mt], bvh[dn][0], bvh[dn][1]);
            }
        }
        __syncthreads();
        if (it < 14) { load_tile(it + 2, it & 1); CP_COMMIT(); }
    }

    __half* ao = g_ao + (size_t)b * NPIX * DIM;
#pragma unroll
    for (int mt = 0; mt < 2; ++mt) {
        const float li0 = 1.f / laccF[mt][0];
        const float li1 = 1.f / laccF[mt][2];
        const int row = qb * 128 + w * 32 + mt * 16 + (lane >> 2);
#pragma unroll
        for (int dn = 0; dn < 4; ++dn) {
            const int col = h * 32 + dn * 8 + 2 * (lane & 3);
            *(__half2*)(ao + (size_t)row * DIM + col) =
                __floats2half2_rn(O[mt][dn][0] * li0, O[mt][dn][1] * li0);
            *(__half2*)(ao + (size_t)(row + 8) * DIM + col) =
                __floats2half2_rn(O[mt][dn][2] * li1, O[mt][dn][3] * li1);
        }
    }
}

// ---------------------------------------------------------------------------
// Kernel 3: output projection on HMMA, pure fp16 (single-term Wo_h * Ao).
// ---------------------------------------------------------------------------
__global__ __launch_bounds__(128) void oproj_kernel(
    const float* __restrict__ Wo, const float* __restrict__ bo,
    float* __restrict__ out)
{
    __shared__ __align__(16) __half woh[64][32];
    __shared__ __align__(16) __half bhs[128][32];

    const int c0 = blockIdx.x * 64;
    const int p0 = blockIdx.y * 128;
    const int b  = blockIdx.z;
    const int t = threadIdx.x, w = t >> 5, lane = t & 31;
    const int lr = lane & 7, lm = lane >> 3;
    const int warp_c = (w & 1) * 32, warp_p = (w >> 1) * 64;

    const __half* ao = g_ao + (size_t)b * NPIX * DIM;

    float acc[2][8][4];
#pragma unroll
    for (int mi = 0; mi < 2; mi++)
#pragma unroll
        for (int ji = 0; ji < 8; ji++)
#pragma unroll
            for (int r = 0; r < 4; r++) acc[mi][ji][r] = 0.f;

    for (int k0 = 0; k0 < DIM; k0 += 32) {
#pragma unroll
        for (int i = 0; i < 2; i++) {
            const int seg = i * 128 + t;
            const int cc = seg >> 2, ck = seg & 3;
            const float* src = Wo + (size_t)(c0 + cc) * DIM + k0 + ck * 8;
            const float4 a = *(const float4*)(src);
            const float4 c = *(const float4*)(src + 4);
            uint4 uh;
            uh.x = h2u(__floats2half2_rn(a.x, a.y));
            uh.y = h2u(__floats2half2_rn(a.z, a.w));
            uh.z = h2u(__floats2half2_rn(c.x, c.y));
            uh.w = h2u(__floats2half2_rn(c.z, c.w));
            const int slot = ck ^ fsw(cc);
            *(uint4*)&woh[cc][slot * 8] = uh;
        }
#pragma unroll
        for (int i = 0; i < 4; i++) {
            const int idx = i * 128 + t;
            const int r = idx >> 2, ck = idx & 3;
            const int slot = ck ^ fsw(r);
            const size_t go = (size_t)(p0 + r) * DIM + k0 + ck * 8;
            *(uint4*)&bhs[r][slot * 8] = *(const uint4*)(ao + go);
        }
        __syncthreads();

        uint32_t awh[2][2][4];
#pragma unroll
        for (int mi = 0; mi < 2; mi++)
#pragma unroll
            for (int kf = 0; kf < 2; kf++) {
                const int row = warp_c + mi * 16 + (lm & 1) * 8 + lr;
                const int slot = (kf * 2 + (lm >> 1)) ^ fsw(row);
                ldm_x4(awh[mi][kf][0], awh[mi][kf][1], awh[mi][kf][2], awh[mi][kf][3],
                       smem_u32(&woh[row][slot * 8]));
            }
#pragma unroll
        for (int ji = 0; ji < 8; ji++) {
            const int prow = warp_p + ji * 8 + lr;
            const int slot = lm ^ fsw(prow);
            uint32_t bbh[4];
            ldm_x4(bbh[0], bbh[1], bbh[2], bbh[3], smem_u32(&bhs[prow][slot * 8]));
#pragma unroll
            for (int mi = 0; mi < 2; mi++) {
                mma16816(acc[mi][ji], awh[mi][0], bbh[0], bbh[1]);
                mma16816(acc[mi][ji], awh[mi][1], bbh[2], bbh[3]);
            }
        }
        __syncthreads();
    }

#pragma unroll
    for (int mi = 0; mi < 2; mi++) {
        const int c = c0 + warp_c + mi * 16 + (lane >> 2);
        const float bias0 = __ldg(bo + c);
        const float bias1 = __ldg(bo + c + 8);
        float* o0 = out + ((size_t)b * CDIM + c) * NPIX;
        float* o1 = out + ((size_t)b * CDIM + c + 8) * NPIX;
#pragma unroll
        for (int ji = 0; ji < 8; ji++) {
            const int pix = p0 + warp_p + ji * 8 + 2 * (lane & 3);
            *(float2*)(o0 + pix) = make_float2(acc[mi][ji][0] + bias0,
                                               acc[mi][ji][1] + bias0);
            *(float2*)(o1 + pix) = make_float2(acc[mi][ji][2] + bias1,
                                               acc[mi][ji][3] + bias1);
        }
    }
}

// ---------------------------------------------------------------------------
extern "C" void kernel_launch(void* const* d_in, const int* in_sizes, int n_in,
                              void* d_out, int out_size)
{
    (void)in_sizes; (void)n_in; (void)out_size;
    const float* x        = (const float*)d_in[0];
    const float* Wq       = (const float*)d_in[1];
    const float* Wk       = (const float*)d_in[2];
    const float* Wv       = (const float*)d_in[3];
    const float* Wo       = (const float*)d_in[4];
    const float* bo       = (const float*)d_in[5];
    const float* rel_bias = (const float*)d_in[6];
    /* d_in[7] = rel_idx unused: idx(i,j) == j - i + 1056 analytically */
    float* out = (float*)d_out;

    static bool attr_done = false;
    if (!attr_done) {
        cudaFuncSetAttribute(attn_kernel,
                             cudaFuncAttributeMaxDynamicSharedMemorySize, ATT_SMEM);
        attr_done = true;
    }

    xcvt_kernel<<<(BATCH * CDIM * NPIX) / (256 * 8), 256>>>(x);
    qkv_kernel<<<dim3(12, 8, 16), 128>>>(Wq, Wk, Wv);
    attn_kernel<<<dim3(8, HEADS, BATCH), 128, ATT_SMEM>>>(rel_bias);
    oproj_kernel<<<dim3(4, 8, 16), 128>>>(Wo, bo, out);
}